// round 16
// baseline (speedup 1.0000x reference)
#include <cuda_runtime.h>
#include <cuda_fp16.h>
#include <float.h>
#include <stdint.h>
#include <math.h>

#define NB 32
#define NL 2048
#define NC 1024
#define KSEL 20
#define NCAND 24
#define GNEPS 1e-5f
#define NLT 16

#define XRANGE 6.5f
#define QX (127.0f / XRANGE)
#define QW (127.0f * 32.0f)
#define SPROD ((XRANGE / 127.0f) * (0.03125f / 127.0f))

// ---------------- scratch (device globals; no allocations allowed) ----------
__device__ __half g_Xhi[(size_t)NB * NL * NC];
__device__ int8_t g_Xq[(size_t)NB * NL * NC];
__device__ int8_t g_Wq[NC * NC];
__device__ __half g_Whi[NC * NC];
__device__ __half g_Wlo[NC * NC];
__device__ __half g_W1hi[NC * NC];
__device__ __half g_W1lo[NC * NC];
__device__ float4 g_cand[NLT * NB * NC];
__device__ float g_cpart[NB * 128 * NC];
__device__ float g_colmean[NB * NC];
__device__ float g_xA[NB * NC];
__device__ float g_xmean[NB * NC];
__device__ float g_tM[NB * NC];
__device__ float g_tA[NB * NC];
__device__ float g_v[NB * NC];
__device__ float g_u[NB * NC];
__device__ float g_s[NB * NL];
__device__ __half g_xghi[NB * KSEL * NC];
__device__ __half g_xglo[NB * KSEL * NC];
__device__ __half g_yhi[NB * KSEL * NC];
__device__ __half g_ylo[NB * KSEL * NC];

// ----------------------------- helpers --------------------------------------
__device__ __forceinline__ uint32_t smem_u32(const void* p) {
    uint32_t a;
    asm("{ .reg .u64 t; cvta.to.shared.u64 t, %1; cvt.u32.u64 %0, t; }"
        : "=r"(a) : "l"(p));
    return a;
}
#define CP_ASYNC16(dst, src) \
    asm volatile("cp.async.cg.shared.global [%0], [%1], 16;" :: "r"(dst), "l"(src) : "memory")
#define CP_COMMIT() asm volatile("cp.async.commit_group;" ::: "memory")
#define CP_WAIT4()  asm volatile("cp.async.wait_group 4;" ::: "memory")
#define CP_WAIT1()  asm volatile("cp.async.wait_group 1;" ::: "memory")
#define MMA16816(c, a0, a1, a2, a3, b0, b1)                                \
    asm volatile("mma.sync.aligned.m16n8k16.row.col.f32.f16.f16.f32 "      \
        "{%0,%1,%2,%3}, {%4,%5,%6,%7}, {%8,%9}, {%0,%1,%2,%3};"            \
        : "+f"((c)[0]), "+f"((c)[1]), "+f"((c)[2]), "+f"((c)[3])           \
        : "r"(a0), "r"(a1), "r"(a2), "r"(a3), "r"(b0), "r"(b1))
#define MMA16832I(c, a0, a1, a2, a3, b0, b1)                               \
    asm volatile("mma.sync.aligned.m16n8k32.row.col.s32.s8.s8.s32 "        \
        "{%0,%1,%2,%3}, {%4,%5,%6,%7}, {%8,%9}, {%0,%1,%2,%3};"            \
        : "+r"((c)[0]), "+r"((c)[1]), "+r"((c)[2]), "+r"((c)[3])           \
        : "r"(a0), "r"(a1), "r"(a2), "r"(a3), "r"(b0), "r"(b1))
#define LDSM4(r0, r1, r2, r3, addr)                                        \
    asm volatile("ldmatrix.sync.aligned.m8n8.x4.shared.b16 {%0,%1,%2,%3}, [%4];" \
        : "=r"(r0), "=r"(r1), "=r"(r2), "=r"(r3) : "r"(addr))

__device__ __forceinline__ void argmax2(float& v, int& i, float ov, int oi) {
    if (ov > v || (ov == v && oi < i)) { v = ov; i = oi; }
}
__device__ __forceinline__ int8_t q8(float x, float s) {
    int v = __float2int_rn(x * s);
    return (int8_t)max(-127, min(127, v));
}

// ---- split x0 -> fp16 hi + int8 quant, fused column-sum partials -----------
__global__ void __launch_bounds__(256)
split_colsum(const float* __restrict__ X0, __half* __restrict__ Xhi,
             int8_t* __restrict__ Xq)
{
    int blk = blockIdx.x;
    int b = blk >> 7, ch = blk & 127;
    int t = threadIdx.x;
    size_t rowbase = ((size_t)b * NL + ch * 16) * NC;
    float4 s = make_float4(0.f, 0.f, 0.f, 0.f);
#pragma unroll
    for (int r = 0; r < 16; r++) {
        size_t off = rowbase + (size_t)r * NC + t * 4;
        float4 v = *(const float4*)(X0 + off);
        s.x += v.x; s.y += v.y; s.z += v.z; s.w += v.w;
        __half2* hp = (__half2*)(Xhi + off);
        hp[0] = __floats2half2_rn(v.x, v.y);
        hp[1] = __floats2half2_rn(v.z, v.w);
        char4 qv;
        qv.x = q8(v.x, QX); qv.y = q8(v.y, QX);
        qv.z = q8(v.z, QX); qv.w = q8(v.w, QX);
        *(char4*)(Xq + off) = qv;
    }
    *(float4*)(g_cpart + (size_t)blk * NC + t * 4) = s;
}

// split W and W1 into fp16 hi/lo; W also to int8 (y selects matrix)
__global__ void wsplit2(const float* __restrict__ W, const float* __restrict__ W1)
{
    const float* src = blockIdx.y ? W1 : W;
    __half* hi = blockIdx.y ? g_W1hi : g_Whi;
    __half* lo = blockIdx.y ? g_W1lo : g_Wlo;
    size_t i = (size_t)blockIdx.x * 256 + threadIdx.x;
    float4 v = ((const float4*)src)[i];
    __half h0 = __float2half_rn(v.x), h1 = __float2half_rn(v.y);
    __half h2 = __float2half_rn(v.z), h3 = __float2half_rn(v.w);
    ((__half2*)hi)[i * 2 + 0] = __halves2half2(h0, h1);
    ((__half2*)hi)[i * 2 + 1] = __halves2half2(h2, h3);
    ((__half2*)lo)[i * 2 + 0] = __floats2half2_rn(v.x - __half2float(h0),
                                                  v.y - __half2float(h1));
    ((__half2*)lo)[i * 2 + 1] = __floats2half2_rn(v.z - __half2float(h2),
                                                  v.w - __half2float(h3));
    if (blockIdx.y == 0) {
        char4 qv;
        qv.x = q8(v.x, QW); qv.y = q8(v.y, QW);
        qv.z = q8(v.z, QW); qv.w = q8(v.w, QW);
        *(char4*)(g_Wq + i * 4) = qv;
    }
}

// one-shot reduce of column-sum partials -> colmean
__global__ void colmean_reduce()
{
    int idx = blockIdx.x * 256 + threadIdx.x;
    int b = idx >> 10, c = idx & 1023;
    float s = 0.f;
#pragma unroll 8
    for (int p = 0; p < 128; p++)
        s += g_cpart[((size_t)(b * 128 + p)) * NC + c];
    g_colmean[idx] = s * (1.0f / NL);
}

// ---------------------------------------------------------------------------
// GEMM1 approx: INT8 mma (m16n8k32, s32 acc), ldmatrix (s8-k32 fragments are
// byte-compatible with f16-k16), 6-stage cp.async k32 pipeline (48KB smem),
// 128x128 CTA tile, 8 warps 64x32, 32 k-steps.
// Epilogue: per-column top-2 (value,row) over the tile's 128 rows -> g_cand.
// ---------------------------------------------------------------------------
#define ST_BYTES 8192

__global__ void __launch_bounds__(256, 2)
gemm1_mma(const int8_t* __restrict__ Xq, const int8_t* __restrict__ Wq)
{
    __shared__ char smem[6 * ST_BYTES];
    const int tid = threadIdx.x;
    const int ntile = blockIdx.x, mtile = blockIdx.y;
    const int wid = tid >> 5, lane = tid & 31;
    const int wm = wid >> 2, wn = wid & 3;
    const int gr = lane >> 2, q = lane & 3;
    const uint32_t sbase = smem_u32(smem);

    // each thread copies one 16B chunk per operand per stage (rows = 32B)
    const int arow = tid >> 1, aseg = tid & 1;
    const size_t gA = (size_t)(mtile * 128 + arow) * NC + aseg * 16;
    const size_t gB = (size_t)(ntile * 128 + arow) * NC + aseg * 16;
    const uint32_t dsto = arow * 32 + ((aseg * 16) ^ (((arow >> 2) & 1) * 16));

    int acc[4][4][4];
#pragma unroll
    for (int i = 0; i < 4; i++)
#pragma unroll
        for (int j = 0; j < 4; j++)
#pragma unroll
            for (int r = 0; r < 4; r++) acc[i][j][r] = 0;

    const int arl = (lane & 7) + ((lane >> 3) & 1) * 8;
    const int ac = lane >> 4;
    uint32_t aoffs[4];
#pragma unroll
    for (int mt = 0; mt < 4; mt++) {
        int r = wm * 64 + mt * 16 + arl;
        aoffs[mt] = r * 32 + ((ac * 16) ^ (((r >> 2) & 1) * 16));
    }
    uint32_t boffs[2];
#pragma unroll
    for (int p = 0; p < 2; p++) {
        int g = lane >> 3;
        int n = wn * 32 + p * 16 + (g >> 1) * 8 + (lane & 7);
        int c = g & 1;
        boffs[p] = 4096 + n * 32 + ((c * 16) ^ (((n >> 2) & 1) * 16));
    }

    auto issue = [&](int s, int k0) {
        uint32_t d = sbase + s * ST_BYTES + dsto;
        CP_ASYNC16(d,         Xq + gA + k0);
        CP_ASYNC16(d + 4096u, Wq + gB + k0);
    };

    issue(0, 0);   CP_COMMIT();
    issue(1, 32);  CP_COMMIT();
    issue(2, 64);  CP_COMMIT();
    issue(3, 96);  CP_COMMIT();
    issue(4, 128); CP_COMMIT();

    for (int ks = 0; ks < 32; ks++) {
        CP_WAIT4();
        __syncthreads();
        if (ks < 27) issue((ks + 5) % 6, (ks + 5) * 32);
        CP_COMMIT();

        const uint32_t st = sbase + (ks % 6) * ST_BYTES;
        uint32_t bf[8];
        LDSM4(bf[0], bf[1], bf[2], bf[3], st + boffs[0]);
        LDSM4(bf[4], bf[5], bf[6], bf[7], st + boffs[1]);
#pragma unroll
        for (int mt = 0; mt < 4; mt++) {
            uint32_t A0, A1, A2, A3;
            LDSM4(A0, A1, A2, A3, st + aoffs[mt]);
#pragma unroll
            for (int nt = 0; nt < 4; nt++)
                MMA16832I(acc[mt][nt], A0, A1, A2, A3, bf[nt * 2], bf[nt * 2 + 1]);
        }
    }

    // ---- epilogue: per-column top-2 (value,row) over 128 rows ----
    __syncthreads();
    float4* sc = (float4*)smem;
    const int lt = mtile & 15, b = mtile >> 4;
    const int lbase = lt * 128;

#pragma unroll
    for (int nt = 0; nt < 4; nt++) {
#pragma unroll
        for (int c = 0; c < 2; c++) {
            int bv1 = INT_MIN, bv2 = INT_MIN;
            int bl1 = 0, bl2 = 0;
#define INS(V, L) do { int _v = (V); int _l = (L);                         \
    if (_v > bv1) { bv2 = bv1; bl2 = bl1; bv1 = _v; bl1 = _l; }            \
    else if (_v > bv2) { bv2 = _v; bl2 = _l; } } while (0)
#pragma unroll
            for (int mt = 0; mt < 4; mt++) {
#pragma unroll
                for (int h = 0; h < 2; h++) {
                    int l = lbase + wm * 64 + mt * 16 + gr + 8 * h;
                    INS(acc[mt][nt][c + 2 * h], l);
                }
            }
#pragma unroll
            for (int o = 4; o <= 16; o <<= 1) {
                int ov1 = __shfl_xor_sync(0xffffffffu, bv1, o);
                int ov2 = __shfl_xor_sync(0xffffffffu, bv2, o);
                int ol1 = __shfl_xor_sync(0xffffffffu, bl1, o);
                int ol2 = __shfl_xor_sync(0xffffffffu, bl2, o);
                INS(ov1, ol1);
                INS(ov2, ol2);
            }
            if (gr == 0) {
                int col = wn * 32 + nt * 8 + q * 2 + c;
                sc[wm * 128 + col] =
                    make_float4((float)bv1 * SPROD, __int_as_float(bl1),
                                (float)bv2 * SPROD, __int_as_float(bl2));
            }
#undef INS
        }
    }
    __syncthreads();
    if (tid < 128) {
        float4 a = sc[tid], o = sc[128 + tid];
        float bv1 = a.x, bv2 = a.z;
        int bl1 = __float_as_int(a.y), bl2 = __float_as_int(a.w);
        float cv[2] = { o.x, o.z };
        int cl[2] = { __float_as_int(o.y), __float_as_int(o.w) };
#pragma unroll
        for (int j = 0; j < 2; j++) {
            if (cv[j] > bv1) { bv2 = bv1; bl2 = bl1; bv1 = cv[j]; bl1 = cl[j]; }
            else if (cv[j] > bv2) { bv2 = cv[j]; bl2 = cl[j]; }
        }
        g_cand[((size_t)lt * NB + b) * NC + ntile * 128 + tid] =
            make_float4(bv1, __int_as_float(bl1), bv2, __int_as_float(bl2));
    }
}

// fused: reduce 16 tile-candidates -> top-3 rows; exact fp32 dots -> x_A
__global__ void __launch_bounds__(256)
exact_max(const float* __restrict__ X0, const float* __restrict__ W,
          const float* __restrict__ bias)
{
    int b = blockIdx.y;
    int wid = threadIdx.x >> 5, lane = threadIdx.x & 31;
    int d = blockIdx.x * 8 + wid;

    float v0 = -FLT_MAX, v1 = -FLT_MAX, v2 = -FLT_MAX;
    int l0 = 0, l1 = 0, l2 = 0;
#pragma unroll
    for (int t = 0; t < NLT; t++) {
        float4 qd = __ldg(&g_cand[((size_t)t * NB + b) * NC + d]);
#pragma unroll
        for (int j = 0; j < 2; j++) {
            float v = j ? qd.z : qd.x;
            int l = __float_as_int(j ? qd.w : qd.y);
            if (v > v0) { v2 = v1; l2 = l1; v1 = v0; l1 = l0; v0 = v; l0 = l; }
            else if (v > v1) { v2 = v1; l2 = l1; v1 = v; l1 = l; }
            else if (v > v2) { v2 = v; l2 = l; }
        }
    }

    const float4* wr = (const float4*)(W + (size_t)d * NC);
    const float4* x1 = (const float4*)(X0 + ((size_t)b * NL + l0) * NC);
    const float4* x2 = (const float4*)(X0 + ((size_t)b * NL + l1) * NC);
    const float4* x3 = (const float4*)(X0 + ((size_t)b * NL + l2) * NC);
    float a1 = 0.f, a2 = 0.f, a3 = 0.f;
#pragma unroll 4
    for (int i = lane; i < NC / 4; i += 32) {
        float4 w4 = __ldg(&wr[i]);
        float4 p = __ldg(&x1[i]);
        a1 += w4.x * p.x + w4.y * p.y + w4.z * p.z + w4.w * p.w;
        p = __ldg(&x2[i]);
        a2 += w4.x * p.x + w4.y * p.y + w4.z * p.z + w4.w * p.w;
        p = __ldg(&x3[i]);
        a3 += w4.x * p.x + w4.y * p.y + w4.z * p.z + w4.w * p.w;
    }
#pragma unroll
    for (int o = 16; o; o >>= 1) {
        a1 += __shfl_xor_sync(0xffffffffu, a1, o);
        a2 += __shfl_xor_sync(0xffffffffu, a2, o);
        a3 += __shfl_xor_sync(0xffffffffu, a3, o);
    }
    if (lane == 0)
        g_xA[b * NC + d] = fmaxf(a1, fmaxf(a2, a3)) + __ldg(bias + d);
}

// out[b,n] = sum_k A[b,k]*M[n,k] + bias[n]
__global__ void __launch_bounds__(256)
small_gemm_T(const float* __restrict__ Ain, const float* __restrict__ M,
             const float* __restrict__ bias, float* __restrict__ out)
{
    int b = blockIdx.y;
    __shared__ __align__(16) float sA[NC];
    int tid = threadIdx.x;
    for (int i = tid; i < NC; i += 256) sA[i] = Ain[b * NC + i];
    __syncthreads();
    int warp = tid >> 5, lane = tid & 31;
    int n = blockIdx.x * 8 + warp;
    const float4* Mr = (const float4*)(M + (size_t)n * NC);
    const float4* Ar = (const float4*)sA;
    float acc = 0.f;
#pragma unroll 4
    for (int i = lane; i < NC / 4; i += 32) {
        float4 m4 = __ldg(&Mr[i]);
        float4 a4 = Ar[i];
        acc += m4.x * a4.x + m4.y * a4.y + m4.z * a4.z + m4.w * a4.w;
    }
#pragma unroll
    for (int o = 16; o; o >>= 1) acc += __shfl_xor_sync(0xffffffffu, acc, o);
    if (lane == 0) out[b * NC + n] = acc + __ldg(bias + n);
}

// batched: z=0 -> (xmean,Wm,bm)->tM ; z=1 -> (xA,Wa,ba)->tA
__global__ void __launch_bounds__(256)
small_gemm_T2(const float* __restrict__ A0, const float* __restrict__ M0,
              const float* __restrict__ b0, float* __restrict__ o0,
              const float* __restrict__ A1, const float* __restrict__ M1,
              const float* __restrict__ b1, float* __restrict__ o1)
{
    const float* Ain = blockIdx.z ? A1 : A0;
    const float* M   = blockIdx.z ? M1 : M0;
    const float* bias= blockIdx.z ? b1 : b0;
    float* out       = blockIdx.z ? o1 : o0;
    int b = blockIdx.y;
    __shared__ __align__(16) float sA[NC];
    int tid = threadIdx.x;
    for (int i = tid; i < NC; i += 256) sA[i] = Ain[b * NC + i];
    __syncthreads();
    int warp = tid >> 5, lane = tid & 31;
    int n = blockIdx.x * 8 + warp;
    const float4* Mr = (const float4*)(M + (size_t)n * NC);
    const float4* Ar = (const float4*)sA;
    float acc = 0.f;
#pragma unroll 4
    for (int i = lane; i < NC / 4; i += 32) {
        float4 m4 = __ldg(&Mr[i]);
        float4 a4 = Ar[i];
        acc += m4.x * a4.x + m4.y * a4.y + m4.z * a4.z + m4.w * a4.w;
    }
#pragma unroll
    for (int o = 16; o; o >>= 1) acc += __shfl_xor_sync(0xffffffffu, acc, o);
    if (lane == 0) out[b * NC + n] = acc + __ldg(bias + n);
}

// v[b,c] = sum_d (gn1[b,d]+gn2[b,d]) * W1[d,c], GroupNorms computed inline
__global__ void __launch_bounds__(256)
gemmN_gn(const float* __restrict__ g1w, const float* __restrict__ g1b,
         const float* __restrict__ g2w, const float* __restrict__ g2b,
         const float* __restrict__ M, float* __restrict__ out)
{
    int b = blockIdx.y;
    int c = blockIdx.x * 256 + threadIdx.x;
    __shared__ __align__(16) float sA[NC];
    int warp = threadIdx.x >> 5, lane = threadIdx.x & 31;
#pragma unroll
    for (int gi = 0; gi < 4; gi++) {
        int grp = warp * 4 + gi;
        int ch = grp * 32 + lane;
        float vM = g_tM[b * NC + ch];
        float vA = g_tA[b * NC + ch];
        float sM = vM, sAs = vA;
#pragma unroll
        for (int o = 16; o; o >>= 1) {
            sM += __shfl_xor_sync(0xffffffffu, sM, o);
            sAs += __shfl_xor_sync(0xffffffffu, sAs, o);
        }
        float mM = sM * (1.f / 32.f), mA = sAs * (1.f / 32.f);
        float dM = vM - mM, dA = vA - mA;
        float qM = dM * dM, qA = dA * dA;
#pragma unroll
        for (int o = 16; o; o >>= 1) {
            qM += __shfl_xor_sync(0xffffffffu, qM, o);
            qA += __shfl_xor_sync(0xffffffffu, qA, o);
        }
        float g1 = dM * rsqrtf(qM * (1.f / 32.f) + GNEPS) * __ldg(g1w + ch) +
                   __ldg(g1b + ch);
        float g2 = dA * rsqrtf(qA * (1.f / 32.f) + GNEPS) * __ldg(g2w + ch) +
                   __ldg(g2b + ch);
        sA[ch] = g1 + g2;
    }
    __syncthreads();
    float acc = 0.f;
#pragma unroll 8
    for (int d = 0; d < NC; d++)
        acc += sA[d] * __ldg(M + (size_t)d * NC + c);
    out[b * NC + c] = acc;
}

// out[b,c] = sum_d A0[b,d]*M[d,c]
__global__ void __launch_bounds__(256)
small_gemm_N(const float* __restrict__ A0, const float* __restrict__ M,
             float* __restrict__ out)
{
    int b = blockIdx.y;
    int c = blockIdx.x * 256 + threadIdx.x;
    __shared__ __align__(16) float sA[NC];
    for (int i = threadIdx.x; i < NC; i += 256) sA[i] = A0[b * NC + i];
    __syncthreads();
    float acc = 0.f;
#pragma unroll 8
    for (int d = 0; d < NC; d++)
        acc += sA[d] * __ldg(M + (size_t)d * NC + c);
    out[b * NC + c] = acc;
}

// approx scores from fp16 Xhi
__global__ void __launch_bounds__(256)
dot_approx(const __half* __restrict__ Xhi)
{
    int b = blockIdx.y;
    __shared__ __align__(16) float su[NC];
    for (int i = threadIdx.x; i < NC; i += 256) su[i] = g_u[b * NC + i];
    __syncthreads();
    int warp = threadIdx.x >> 5, lane = threadIdx.x & 31;
    int l = blockIdx.x * 8 + warp;
    const float4* xr = (const float4*)(Xhi + ((size_t)b * NL + l) * NC);
    float acc = 0.f;
#pragma unroll 4
    for (int i = lane; i < NC / 8; i += 32) {
        float4 h8 = __ldg(&xr[i]);
        const __half2* hp = (const __half2*)&h8;
        const float4* u0 = (const float4*)&su[i * 8];
        float4 ua = u0[0], ub = u0[1];
        float2 p0 = __half22float2(hp[0]);
        float2 p1 = __half22float2(hp[1]);
        float2 p2 = __half22float2(hp[2]);
        float2 p3 = __half22float2(hp[3]);
        acc += p0.x * ua.x + p0.y * ua.y + p1.x * ua.z + p1.y * ua.w;
        acc += p2.x * ub.x + p2.y * ub.y + p3.x * ub.z + p3.y * ub.w;
    }
#pragma unroll
    for (int o = 16; o; o >>= 1) acc += __shfl_xor_sync(0xffffffffu, acc, o);
    if (lane == 0) g_s[b * NL + l] = acc;
}

// ---------------------------------------------------------------------------
// fused selection: top-24 approx -> exact fp32 rescue -> ordered top-20 ->
// gather+split selected rows. one 768-thread block per batch.
// ---------------------------------------------------------------------------
__global__ void __launch_bounds__(768)
select_kernel(const float* __restrict__ X0)
{
    __shared__ __align__(16) float su[NC];
    __shared__ __align__(16) float vals[NL];
    __shared__ float lmax[256];
    __shared__ int   lidx[256];
    __shared__ float wmax[8];
    __shared__ int   widx[8];
    __shared__ int   sowner;
    __shared__ int   scand[NCAND];
    __shared__ float sval[NCAND];
    __shared__ int   sidx[NCAND];
    __shared__ int   stop[KSEL];
    int b = blockIdx.x;
    int tid = threadIdx.x;
    int warp = tid >> 5, lane = tid & 31;

    for (int i = tid; i < NC; i += 768) su[i] = g_u[b * NC + i];
    for (int i = tid; i < NL; i += 768) vals[i] = g_s[b * NL + i];
    __syncthreads();

    if (tid < 256) {
        float m = -FLT_MAX; int mi = 0x7fffffff;
#pragma unroll
        for (int r = 0; r < 8; r++) {
            int i = tid + r * 256;
            argmax2(m, mi, vals[i], i);
        }
        lmax[tid] = m; lidx[tid] = mi;
    }
    __syncthreads();
    for (int it = 0; it < NCAND; it++) {
        if (tid < 256) {
            float v = lmax[tid]; int i = lidx[tid];
#pragma unroll
            for (int o = 16; o; o >>= 1)
                argmax2(v, i, __shfl_xor_sync(0xffffffffu, v, o),
                              __shfl_xor_sync(0xffffffffu, i, o));
            if (lane == 0) { wmax[warp] = v; widx[warp] = i; }
        }
        __syncthreads();
        if (tid == 0) {
            float bv = wmax[0]; int bi = widx[0];
#pragma unroll
            for (int w = 1; w < 8; w++) argmax2(bv, bi, wmax[w], widx[w]);
            scand[it] = bi;
            vals[bi] = -FLT_MAX;
            sowner = bi & 255;
        }
        __syncthreads();
        if (tid == sowner) {
            float m = -FLT_MAX; int mi = 0x7fffffff;
#pragma unroll
            for (int r = 0; r < 8; r++) {
                int i2 = tid + r * 256;
                argmax2(m, mi, vals[i2], i2);
            }
            lmax[tid] = m; lidx[tid] = mi;
        }
        __syncthreads();
    }

    if (warp < NCAND) {
        int l = scand[warp];
        const float4* xr = (const float4*)(X0 + ((size_t)b * NL + l) * NC);
        const float4* ur = (const float4*)su;
        float acc = 0.f;
#pragma unroll 4
        for (int i = lane; i < NC / 4; i += 32) {
            float4 x = __ldg(&xr[i]);
            float4 u = ur[i];
            acc += x.x * u.x + x.y * u.y + x.z * u.z + x.w * u.w;
        }
#pragma unroll
        for (int o = 16; o; o >>= 1) acc += __shfl_xor_sync(0xffffffffu, acc, o);
        if (lane == 0) { sval[warp] = acc; sidx[warp] = l; }
    }
    __syncthreads();
    if (warp == 0) {
        float v = (lane < NCAND) ? sval[lane] : -FLT_MAX;
        int i = (lane < NCAND) ? sidx[lane] : 0x7fffffff;
        for (int it = 0; it < KSEL; it++) {
            float bv = v; int bi = i;
#pragma unroll
            for (int o = 16; o; o >>= 1)
                argmax2(bv, bi, __shfl_xor_sync(0xffffffffu, bv, o),
                                __shfl_xor_sync(0xffffffffu, bi, o));
            if (i == bi && v == bv) v = -FLT_MAX;
            if (lane == 0) stop[it] = bi;
        }
    }
    __syncthreads();

    for (int idx = tid; idx < KSEL * 256; idx += 768) {
        int r = idx >> 8, t = idx & 255;
        int l = stop[r];
        size_t dst = ((size_t)(b * KSEL + r)) * NC + t * 4;
        float4 v = *(const float4*)(X0 + ((size_t)b * NL + l) * NC + t * 4);
        __half h0 = __float2half_rn(v.x), h1 = __float2half_rn(v.y);
        __half h2 = __float2half_rn(v.z), h3 = __float2half_rn(v.w);
        __half2* hp = (__half2*)(g_xghi + dst);
        hp[0] = __halves2half2(h0, h1);
        hp[1] = __halves2half2(h2, h3);
        __half2* lp = (__half2*)(g_xglo + dst);
        lp[0] = __floats2half2_rn(v.x - __half2float(h0), v.y - __half2float(h1));
        lp[1] = __floats2half2_rn(v.z - __half2float(h2), v.w - __half2float(h3));
    }
}

// ---------------------------------------------------------------------------
// fp16x3 GEMM for selected rows: M-tile 64, N-tile 128, 8 warps 32x32.
// ---------------------------------------------------------------------------
#define ST3_BYTES 12288

template <int SPLIT>
__global__ void __launch_bounds__(256, 1)
gemm_x3(const __half* __restrict__ Ahi, const __half* __restrict__ Alo,
        const __half* __restrict__ Bhi, const __half* __restrict__ Blo,
        const float* __restrict__ bias, float* __restrict__ outf,
        __half* __restrict__ ohi, __half* __restrict__ olo)
{
    __shared__ char smem[3 * ST3_BYTES];
    const int tid = threadIdx.x;
    const int ntile = blockIdx.x, mtile = blockIdx.y;
    const int wid = tid >> 5, lane = tid & 31;
    const int wm = wid >> 2, wn = wid & 3;
    const int gr = lane >> 2, q = lane & 3;
    const uint32_t sbase = smem_u32(smem);

    const int arow = (tid & 127) >> 1, aseg = tid & 1;
    const int brow = tid >> 1, bseg = tid & 1;
    const size_t gA = (size_t)(mtile * 64 + arow) * NC + aseg * 8;
    const size_t gB = (size_t)(ntile * 128 + brow) * NC + bseg * 8;
    const uint32_t dstoA = arow * 32 + ((aseg * 16) ^ (((arow >> 2) & 1) * 16));
    const uint32_t dstoB = brow * 32 + ((bseg * 16) ^ (((brow >> 2) & 1) * 16));
    const bool doA = tid < 128;

    float acc[2][4][4];
#pragma unroll
    for (int i = 0; i < 2; i++)
#pragma unroll
        for (int j = 0; j < 4; j++)
#pragma unroll
            for (int r = 0; r < 4; r++) acc[i][j][r] = 0.f;

    const int arl = (lane & 7) + ((lane >> 3) & 1) * 8;
    const int ac = lane >> 4;
    uint32_t aoffs[2];
#pragma unroll
    for (int mt = 0; mt < 2; mt++) {
        int r = wm * 32 + mt * 16 + arl;
        aoffs[mt] = r * 32 + ((ac * 16) ^ (((r >> 2) & 1) * 16));
    }
    uint32_t boffs[2];
#pragma unroll
    for (int p = 0; p < 2; p++) {
        int g = lane >> 3;
        int n = wn * 32 + p * 16 + (g >> 1) * 8 + (lane & 7);
        int c = g & 1;
        boffs[p] = n * 32 + ((c * 16) ^ (((n >> 2) & 1) * 16));
    }

    auto issue = [&](int s, int k0) {
        uint32_t base = sbase + s * ST3_BYTES;
        if (doA) {
            CP_ASYNC16(base + dstoA,         Ahi + gA + k0);
            CP_ASYNC16(base + 2048u + dstoA, Alo + gA + k0);
        }
        CP_ASYNC16(base + 4096u + dstoB, Bhi + gB + k0);
        CP_ASYNC16(base + 8192u + dstoB, Blo + gB + k0);
    };

    issue(0, 0);  CP_COMMIT();
    issue(1, 16); CP_COMMIT();

    for (int ks = 0; ks < 64; ks++) {
        CP_WAIT1();
        __syncthreads();
        int s = ks % 3;
        if (ks < 62) issue((ks + 2) % 3, (ks + 2) * 16);
        CP_COMMIT();

        const uint32_t st = sbase + s * ST3_BYTES;
        uint32_t bh[8], bl[8];
        LDSM4(bh[0], bh[1], bh[2], bh[3], st + 4096u + boffs[0]);
        LDSM4(bh[4], bh[5], bh[6], bh[7], st + 4096u + boffs[1]);
        LDSM4(bl[0], bl[1], bl[2], bl[3], st + 8192u + boffs[0]);
        LDSM4(bl[4], bl[5], bl[6], bl[7], st + 8192u + boffs[1]);
#pragma unroll
        for (int mt = 0; mt < 2; mt++) {
            uint32_t H0, H1, H2, H3, L0, L1, L2, L3;
            LDSM4(H0, H1, H2, H3, st + aoffs[mt]);
#pragma unroll
            for (int nt = 0; nt < 4; nt++)
                MMA16816(acc[mt][nt], H0, H1, H2, H3, bh[nt * 2], bh[nt * 2 + 1]);
#pragma unroll
            for (int nt = 0; nt < 4; nt++)
                MMA16816(acc[mt][nt], H0, H1, H2, H3, bl[nt * 2], bl[nt * 2 + 1]);
            LDSM4(L0, L1, L2, L3, st + 2048u + aoffs[mt]);
#pragma unroll
            for (int nt = 0; nt < 4; nt++)
                MMA16816(acc[mt][nt], L0, L1, L2, L3, bh[nt * 2], bh[nt * 2 + 1]);
        }
    }

#pragma unroll
    for (int mt = 0; mt < 2; mt++)
#pragma unroll
        for (int nt = 0; nt < 4; nt++)
#pragma unroll
            for (int r = 0; r < 4; r++) {
                int m = mtile * 64 + wm * 32 + mt * 16 + gr + 8 * (r >> 1);
                int n = ntile * 128 + wn * 32 + nt * 8 + q * 2 + (r & 1);
                float v = acc[mt][nt][r] + __ldg(bias + n);
                if (SPLIT) {
                    __half h = __float2half_rn(v);
                    ohi[(size_t)m * NC + n] = h;
                    olo[(size_t)m * NC + n] =
                        __float2half_rn(v - __half2float(h));
                } else {
                    outf[(size_t)m * NC + n] = v;
                }
            }
}

// ---------------------------------------------------------------------------
static void* symp(const void* symbol)
{
    void* p = nullptr;
    cudaGetSymbolAddress(&p, symbol);
    return p;
}

extern "C" void kernel_launch(void* const* d_in, const int* in_sizes, int n_in,
                              void* d_out, int out_size)
{
    const float* x0  = (const float*)d_in[0];
    const float* W   = (const float*)d_in[1];
    const float* b   = (const float*)d_in[2];
    const float* W1  = (const float*)d_in[3];
    const float* b1  = (const float*)d_in[4];
    const float* Wm  = (const float*)d_in[5];
    const float* bm  = (const float*)d_in[6];
    const float* Wa  = (const float*)d_in[7];
    const float* ba  = (const float*)d_in[8];
    const float* g1w = (const float*)d_in[9];
    const float* g1b = (const float*)d_in[10];
    const float* g2w = (const float*)d_in[11];
    const float* g2b = (const float*)d_in[12];
    float* out = (float*)d_out;

    __half* p_Xhi  = (__half*)symp(g_Xhi);
    int8_t* p_Xq   = (int8_t*)symp(g_Xq);
    int8_t* p_Wq   = (int8_t*)symp(g_Wq);
    __half* p_Whi  = (__half*)symp(g_Whi);
    __half* p_Wlo  = (__half*)symp(g_Wlo);
    __half* p_W1hi = (__half*)symp(g_W1hi);
    __half* p_W1lo = (__half*)symp(g_W1lo);
    __half* p_xghi = (__half*)symp(g_xghi);
    __half* p_xglo = (__half*)symp(g_xglo);
    __half* p_yhi  = (__half*)symp(g_yhi);
    __half* p_ylo  = (__half*)symp(g_ylo);
    float* p_colmean = (float*)symp(g_colmean);
    float* p_xmean = (float*)symp(g_xmean);
    float* p_xA    = (float*)symp(g_xA);
    float* p_tM    = (float*)symp(g_tM);
    float* p_tA    = (float*)symp(g_tA);
    float* p_v     = (float*)symp(g_v);
    float* p_u     = (float*)symp(g_u);

    // 0) splits (fp16 + int8) + one-shot colmean reduce
    split_colsum<<<NB * 128, 256>>>(x0, p_Xhi, p_Xq);
    dim3 gws((NC * NC / 4) / 256, 2);
    wsplit2<<<gws, 256>>>(W, W1);
    colmean_reduce<<<(NB * NC) / 256, 256>>>();

    // 1) INT8 approx GEMM1 + fused candidate-reduce/exact-max (top-3)
    dim3 g1(8, 512);
    gemm1_mma<<<g1, 256>>>(p_Xq, p_Wq);
    dim3 gex(NC / 8, NB);
    exact_max<<<gex, 256>>>(x0, W, b);

    // 2) mean path + pooled branches
    dim3 gst(NC / 8, NB);
    small_gemm_T<<<gst, 256>>>(p_colmean, W, b, p_xmean);
    dim3 gst2(NC / 8, NB, 2);
    small_gemm_T2<<<gst2, 256>>>(p_xmean, Wm, bm, p_tM, p_xA, Wa, ba, p_tA);

    // 3) v = W1^T(gn1+gn2) with inline GroupNorm; u = W^T v
    dim3 gsn(NC / 256, NB);
    gemmN_gn<<<gsn, 256>>>(g1w, g1b, g2w, g2b, W1, p_v);
    small_gemm_N<<<gsn, 256>>>(p_v, W, p_u);

    // 4) approx scores, fused top-24/rescue/gather, fp16x3 recompute
    dim3 gdot(NL / 8, NB);
    dot_approx<<<gdot, 256>>>(p_Xhi);
    select_kernel<<<NB, 768>>>(x0);
    dim3 gg2(8, (NB * KSEL) / 64);
    gemm_x3<1><<<gg2, 256>>>(p_xghi, p_xglo, p_Whi, p_Wlo, b,
                             nullptr, p_yhi, p_ylo);
    gemm_x3<0><<<gg2, 256>>>(p_yhi, p_ylo, p_W1hi, p_W1lo, b1,
                             out, nullptr, nullptr);
}

// round 17
// speedup vs baseline: 1.7098x; 1.7098x over previous
#include <cuda_runtime.h>
#include <cuda_fp16.h>
#include <float.h>
#include <stdint.h>
#include <math.h>

#define NB 32
#define NL 2048
#define NC 1024
#define KSEL 20
#define NCAND 24
#define GNEPS 1e-5f
#define NLT 16

// ---------------- scratch (device globals; no allocations allowed) ----------
__device__ __half g_Xhi[(size_t)NB * NL * NC];
__device__ __half g_Whi[NC * NC];
__device__ __half g_Wlo[NC * NC];
__device__ __half g_W1hi[NC * NC];
__device__ __half g_W1lo[NC * NC];
__device__ float4 g_cand[NLT * NB * NC];
__device__ float g_cpart[NB * 128 * NC];
__device__ float g_colmean[NB * NC];
__device__ float g_xA[NB * NC];
__device__ float g_xmean[NB * NC];
__device__ float g_tM[NB * NC];
__device__ float g_tA[NB * NC];
__device__ float g_v[NB * NC];
__device__ float g_u[NB * NC];
__device__ float g_s[NB * NL];
__device__ __half g_xghi[NB * KSEL * NC];
__device__ __half g_xglo[NB * KSEL * NC];
__device__ __half g_yhi[NB * KSEL * NC];
__device__ __half g_ylo[NB * KSEL * NC];

// ----------------------------- helpers --------------------------------------
__device__ __forceinline__ uint32_t smem_u32(const void* p) {
    uint32_t a;
    asm("{ .reg .u64 t; cvta.to.shared.u64 t, %1; cvt.u32.u64 %0, t; }"
        : "=r"(a) : "l"(p));
    return a;
}
#define CP_ASYNC16(dst, src) \
    asm volatile("cp.async.cg.shared.global [%0], [%1], 16;" :: "r"(dst), "l"(src) : "memory")
#define CP_COMMIT() asm volatile("cp.async.commit_group;" ::: "memory")
#define CP_WAIT4()  asm volatile("cp.async.wait_group 4;" ::: "memory")
#define CP_WAIT1()  asm volatile("cp.async.wait_group 1;" ::: "memory")
#define MMA16816(c, a0, a1, a2, a3, b0, b1)                                \
    asm volatile("mma.sync.aligned.m16n8k16.row.col.f32.f16.f16.f32 "      \
        "{%0,%1,%2,%3}, {%4,%5,%6,%7}, {%8,%9}, {%0,%1,%2,%3};"            \
        : "+f"((c)[0]), "+f"((c)[1]), "+f"((c)[2]), "+f"((c)[3])           \
        : "r"(a0), "r"(a1), "r"(a2), "r"(a3), "r"(b0), "r"(b1))
#define LDSM4(r0, r1, r2, r3, addr)                                        \
    asm volatile("ldmatrix.sync.aligned.m8n8.x4.shared.b16 {%0,%1,%2,%3}, [%4];" \
        : "=r"(r0), "=r"(r1), "=r"(r2), "=r"(r3) : "r"(addr))

__device__ __forceinline__ void argmax2(float& v, int& i, float ov, int oi) {
    if (ov > v || (ov == v && oi < i)) { v = ov; i = oi; }
}

// ---- split x0 -> fp16 hi, fused per-16-row column-sum partials -------------
__global__ void __launch_bounds__(256)
split_colsum(const float* __restrict__ X0, __half* __restrict__ Xhi)
{
    int blk = blockIdx.x;
    int b = blk >> 7, ch = blk & 127;
    int t = threadIdx.x;
    size_t rowbase = ((size_t)b * NL + ch * 16) * NC;
    float4 s = make_float4(0.f, 0.f, 0.f, 0.f);
#pragma unroll
    for (int r = 0; r < 16; r++) {
        float4 v = *(const float4*)(X0 + rowbase + (size_t)r * NC + t * 4);
        s.x += v.x; s.y += v.y; s.z += v.z; s.w += v.w;
        __half2* hp = (__half2*)(Xhi + rowbase + (size_t)r * NC + t * 4);
        hp[0] = __floats2half2_rn(v.x, v.y);
        hp[1] = __floats2half2_rn(v.z, v.w);
    }
    *(float4*)(g_cpart + (size_t)blk * NC + t * 4) = s;
}

// split W and W1 into fp16 hi/lo in one launch (y selects matrix)
__global__ void wsplit2(const float* __restrict__ W, const float* __restrict__ W1)
{
    const float* src = blockIdx.y ? W1 : W;
    __half* hi = blockIdx.y ? g_W1hi : g_Whi;
    __half* lo = blockIdx.y ? g_W1lo : g_Wlo;
    size_t i = (size_t)blockIdx.x * 256 + threadIdx.x;
    float4 v = ((const float4*)src)[i];
    __half h0 = __float2half_rn(v.x), h1 = __float2half_rn(v.y);
    __half h2 = __float2half_rn(v.z), h3 = __float2half_rn(v.w);
    ((__half2*)hi)[i * 2 + 0] = __halves2half2(h0, h1);
    ((__half2*)hi)[i * 2 + 1] = __halves2half2(h2, h3);
    ((__half2*)lo)[i * 2 + 0] = __floats2half2_rn(v.x - __half2float(h0),
                                                  v.y - __half2float(h1));
    ((__half2*)lo)[i * 2 + 1] = __floats2half2_rn(v.z - __half2float(h2),
                                                  v.w - __half2float(h3));
}

// one-shot reduce of column-sum partials -> colmean
__global__ void colmean_reduce()
{
    int idx = blockIdx.x * 256 + threadIdx.x;
    int b = idx >> 10, c = idx & 1023;
    float s = 0.f;
#pragma unroll 8
    for (int p = 0; p < 128; p++)
        s += g_cpart[((size_t)(b * 128 + p)) * NC + c];
    g_colmean[idx] = s * (1.0f / NL);
}

// ---------------------------------------------------------------------------
// GEMM1 approx: single fp16 product, fp32 accumulators, ldmatrix, 6-stage
// cp.async k16 pipeline (48KB smem), 128x128 CTA tile, 8 warps 64x32.
// Epilogue: per-column top-2 (value,row) over the tile's 128 rows -> g_cand.
// ---------------------------------------------------------------------------
#define ST_BYTES 8192

__global__ void __launch_bounds__(256, 2)
gemm1_mma(const __half* __restrict__ Xhi, const __half* __restrict__ Whi)
{
    __shared__ char smem[6 * ST_BYTES];
    const int tid = threadIdx.x;
    const int ntile = blockIdx.x, mtile = blockIdx.y;
    const int wid = tid >> 5, lane = tid & 31;
    const int wm = wid >> 2, wn = wid & 3;
    const int gr = lane >> 2, q = lane & 3;
    const uint32_t sbase = smem_u32(smem);

    const int arow = tid >> 1, aseg = tid & 1;
    const size_t gA = (size_t)(mtile * 128 + arow) * NC + aseg * 8;
    const size_t gB = (size_t)(ntile * 128 + arow) * NC + aseg * 8;
    const uint32_t dsto = arow * 32 + ((aseg * 16) ^ (((arow >> 2) & 1) * 16));

    float acc[4][4][4];
#pragma unroll
    for (int i = 0; i < 4; i++)
#pragma unroll
        for (int j = 0; j < 4; j++)
#pragma unroll
            for (int r = 0; r < 4; r++) acc[i][j][r] = 0.f;

    const int arl = (lane & 7) + ((lane >> 3) & 1) * 8;
    const int ac = lane >> 4;
    uint32_t aoffs[4];
#pragma unroll
    for (int mt = 0; mt < 4; mt++) {
        int r = wm * 64 + mt * 16 + arl;
        aoffs[mt] = r * 32 + ((ac * 16) ^ (((r >> 2) & 1) * 16));
    }
    uint32_t boffs[2];
#pragma unroll
    for (int p = 0; p < 2; p++) {
        int g = lane >> 3;
        int n = wn * 32 + p * 16 + (g >> 1) * 8 + (lane & 7);
        int c = g & 1;
        boffs[p] = 4096 + n * 32 + ((c * 16) ^ (((n >> 2) & 1) * 16));
    }

    auto issue = [&](int s, int k0) {
        uint32_t d = sbase + s * ST_BYTES + dsto;
        CP_ASYNC16(d,         Xhi + gA + k0);
        CP_ASYNC16(d + 4096u, Whi + gB + k0);
    };

    issue(0, 0);  CP_COMMIT();
    issue(1, 16); CP_COMMIT();
    issue(2, 32); CP_COMMIT();
    issue(3, 48); CP_COMMIT();
    issue(4, 64); CP_COMMIT();

    for (int ks = 0; ks < 64; ks++) {
        CP_WAIT4();
        __syncthreads();
        if (ks < 59) issue((ks + 5) % 6, (ks + 5) * 16);
        CP_COMMIT();

        const uint32_t st = sbase + (ks % 6) * ST_BYTES;
        uint32_t bf[8];
        LDSM4(bf[0], bf[1], bf[2], bf[3], st + boffs[0]);
        LDSM4(bf[4], bf[5], bf[6], bf[7], st + boffs[1]);
#pragma unroll
        for (int mt = 0; mt < 4; mt++) {
            uint32_t A0, A1, A2, A3;
            LDSM4(A0, A1, A2, A3, st + aoffs[mt]);
#pragma unroll
            for (int nt = 0; nt < 4; nt++)
                MMA16816(acc[mt][nt], A0, A1, A2, A3, bf[nt * 2], bf[nt * 2 + 1]);
        }
    }

    // ---- epilogue: per-column top-2 (value,row) over 128 rows ----
    __syncthreads();
    float4* sc = (float4*)smem;
    const int lt = mtile & 15, b = mtile >> 4;
    const int lbase = lt * 128;

#pragma unroll
    for (int nt = 0; nt < 4; nt++) {
#pragma unroll
        for (int c = 0; c < 2; c++) {
            float bv1 = -FLT_MAX, bv2 = -FLT_MAX;
            int bl1 = 0, bl2 = 0;
#define INS(V, L) do { float _v = (V); int _l = (L);                       \
    if (_v > bv1) { bv2 = bv1; bl2 = bl1; bv1 = _v; bl1 = _l; }            \
    else if (_v > bv2) { bv2 = _v; bl2 = _l; } } while (0)
#pragma unroll
            for (int mt = 0; mt < 4; mt++) {
#pragma unroll
                for (int h = 0; h < 2; h++) {
                    int l = lbase + wm * 64 + mt * 16 + gr + 8 * h;
                    INS(acc[mt][nt][c + 2 * h], l);
                }
            }
#pragma unroll
            for (int o = 4; o <= 16; o <<= 1) {
                float ov1 = __shfl_xor_sync(0xffffffffu, bv1, o);
                float ov2 = __shfl_xor_sync(0xffffffffu, bv2, o);
                int ol1 = __shfl_xor_sync(0xffffffffu, bl1, o);
                int ol2 = __shfl_xor_sync(0xffffffffu, bl2, o);
                INS(ov1, ol1);
                INS(ov2, ol2);
            }
            if (gr == 0) {
                int col = wn * 32 + nt * 8 + q * 2 + c;
                sc[wm * 128 + col] = make_float4(bv1, __int_as_float(bl1),
                                                 bv2, __int_as_float(bl2));
            }
#undef INS
        }
    }
    __syncthreads();
    if (tid < 128) {
        float4 a = sc[tid], o = sc[128 + tid];
        float bv1 = a.x, bv2 = a.z;
        int bl1 = __float_as_int(a.y), bl2 = __float_as_int(a.w);
        float cv[2] = { o.x, o.z };
        int cl[2] = { __float_as_int(o.y), __float_as_int(o.w) };
#pragma unroll
        for (int j = 0; j < 2; j++) {
            if (cv[j] > bv1) { bv2 = bv1; bl2 = bl1; bv1 = cv[j]; bl1 = cl[j]; }
            else if (cv[j] > bv2) { bv2 = cv[j]; bl2 = cl[j]; }
        }
        g_cand[((size_t)lt * NB + b) * NC + ntile * 128 + tid] =
            make_float4(bv1, __int_as_float(bl1), bv2, __int_as_float(bl2));
    }
}

// fused: reduce 16 tile-candidates -> top-2 rows; exact fp32 dots -> x_A
__global__ void __launch_bounds__(256)
exact_max(const float* __restrict__ X0, const float* __restrict__ W,
          const float* __restrict__ bias)
{
    int b = blockIdx.y;
    int wid = threadIdx.x >> 5, lane = threadIdx.x & 31;
    int d = blockIdx.x * 8 + wid;

    float v0 = -FLT_MAX, v1 = -FLT_MAX;
    int l0 = 0, l1 = 0;
#pragma unroll
    for (int t = 0; t < NLT; t++) {
        float4 qd = __ldg(&g_cand[((size_t)t * NB + b) * NC + d]);
#pragma unroll
        for (int j = 0; j < 2; j++) {
            float v = j ? qd.z : qd.x;
            int l = __float_as_int(j ? qd.w : qd.y);
            if (v > v0) { v1 = v0; l1 = l0; v0 = v; l0 = l; }
            else if (v > v1) { v1 = v; l1 = l; }
        }
    }

    const float4* wr = (const float4*)(W + (size_t)d * NC);
    const float4* x1 = (const float4*)(X0 + ((size_t)b * NL + l0) * NC);
    const float4* x2 = (const float4*)(X0 + ((size_t)b * NL + l1) * NC);
    float a1 = 0.f, a2 = 0.f;
#pragma unroll 4
    for (int i = lane; i < NC / 4; i += 32) {
        float4 w4 = __ldg(&wr[i]);
        float4 p = __ldg(&x1[i]);
        a1 += w4.x * p.x + w4.y * p.y + w4.z * p.z + w4.w * p.w;
        p = __ldg(&x2[i]);
        a2 += w4.x * p.x + w4.y * p.y + w4.z * p.z + w4.w * p.w;
    }
#pragma unroll
    for (int o = 16; o; o >>= 1) {
        a1 += __shfl_xor_sync(0xffffffffu, a1, o);
        a2 += __shfl_xor_sync(0xffffffffu, a2, o);
    }
    if (lane == 0)
        g_xA[b * NC + d] = fmaxf(a1, a2) + __ldg(bias + d);
}

// out[b,n] = sum_k A[b,k]*M[n,k] + bias[n]
__global__ void __launch_bounds__(256)
small_gemm_T(const float* __restrict__ Ain, const float* __restrict__ M,
             const float* __restrict__ bias, float* __restrict__ out)
{
    int b = blockIdx.y;
    __shared__ __align__(16) float sA[NC];
    int tid = threadIdx.x;
    for (int i = tid; i < NC; i += 256) sA[i] = Ain[b * NC + i];
    __syncthreads();
    int warp = tid >> 5, lane = tid & 31;
    int n = blockIdx.x * 8 + warp;
    const float4* Mr = (const float4*)(M + (size_t)n * NC);
    const float4* Ar = (const float4*)sA;
    float acc = 0.f;
#pragma unroll 4
    for (int i = lane; i < NC / 4; i += 32) {
        float4 m4 = __ldg(&Mr[i]);
        float4 a4 = Ar[i];
        acc += m4.x * a4.x + m4.y * a4.y + m4.z * a4.z + m4.w * a4.w;
    }
#pragma unroll
    for (int o = 16; o; o >>= 1) acc += __shfl_xor_sync(0xffffffffu, acc, o);
    if (lane == 0) out[b * NC + n] = acc + __ldg(bias + n);
}

// batched: z=0 -> (xmean,Wm,bm)->tM ; z=1 -> (xA,Wa,ba)->tA
__global__ void __launch_bounds__(256)
small_gemm_T2(const float* __restrict__ A0, const float* __restrict__ M0,
              const float* __restrict__ b0, float* __restrict__ o0,
              const float* __restrict__ A1, const float* __restrict__ M1,
              const float* __restrict__ b1, float* __restrict__ o1)
{
    const float* Ain = blockIdx.z ? A1 : A0;
    const float* M   = blockIdx.z ? M1 : M0;
    const float* bias= blockIdx.z ? b1 : b0;
    float* out       = blockIdx.z ? o1 : o0;
    int b = blockIdx.y;
    __shared__ __align__(16) float sA[NC];
    int tid = threadIdx.x;
    for (int i = tid; i < NC; i += 256) sA[i] = Ain[b * NC + i];
    __syncthreads();
    int warp = tid >> 5, lane = tid & 31;
    int n = blockIdx.x * 8 + warp;
    const float4* Mr = (const float4*)(M + (size_t)n * NC);
    const float4* Ar = (const float4*)sA;
    float acc = 0.f;
#pragma unroll 4
    for (int i = lane; i < NC / 4; i += 32) {
        float4 m4 = __ldg(&Mr[i]);
        float4 a4 = Ar[i];
        acc += m4.x * a4.x + m4.y * a4.y + m4.z * a4.z + m4.w * a4.w;
    }
#pragma unroll
    for (int o = 16; o; o >>= 1) acc += __shfl_xor_sync(0xffffffffu, acc, o);
    if (lane == 0) out[b * NC + n] = acc + __ldg(bias + n);
}

// v[b,c] = sum_d (gn1[b,d]+gn2[b,d]) * W1[d,c], GroupNorms computed inline
__global__ void __launch_bounds__(256)
gemmN_gn(const float* __restrict__ g1w, const float* __restrict__ g1b,
         const float* __restrict__ g2w, const float* __restrict__ g2b,
         const float* __restrict__ M, float* __restrict__ out)
{
    int b = blockIdx.y;
    int c = blockIdx.x * 256 + threadIdx.x;
    __shared__ __align__(16) float sA[NC];
    int warp = threadIdx.x >> 5, lane = threadIdx.x & 31;
#pragma unroll
    for (int gi = 0; gi < 4; gi++) {
        int grp = warp * 4 + gi;
        int ch = grp * 32 + lane;
        float vM = g_tM[b * NC + ch];
        float vA = g_tA[b * NC + ch];
        float sM = vM, sAs = vA;
#pragma unroll
        for (int o = 16; o; o >>= 1) {
            sM += __shfl_xor_sync(0xffffffffu, sM, o);
            sAs += __shfl_xor_sync(0xffffffffu, sAs, o);
        }
        float mM = sM * (1.f / 32.f), mA = sAs * (1.f / 32.f);
        float dM = vM - mM, dA = vA - mA;
        float qM = dM * dM, qA = dA * dA;
#pragma unroll
        for (int o = 16; o; o >>= 1) {
            qM += __shfl_xor_sync(0xffffffffu, qM, o);
            qA += __shfl_xor_sync(0xffffffffu, qA, o);
        }
        float g1 = dM * rsqrtf(qM * (1.f / 32.f) + GNEPS) * __ldg(g1w + ch) +
                   __ldg(g1b + ch);
        float g2 = dA * rsqrtf(qA * (1.f / 32.f) + GNEPS) * __ldg(g2w + ch) +
                   __ldg(g2b + ch);
        sA[ch] = g1 + g2;
    }
    __syncthreads();
    float acc = 0.f;
#pragma unroll 8
    for (int d = 0; d < NC; d++)
        acc += sA[d] * __ldg(M + (size_t)d * NC + c);
    out[b * NC + c] = acc;
}

// out[b,c] = sum_d A0[b,d]*M[d,c]
__global__ void __launch_bounds__(256)
small_gemm_N(const float* __restrict__ A0, const float* __restrict__ M,
             float* __restrict__ out)
{
    int b = blockIdx.y;
    int c = blockIdx.x * 256 + threadIdx.x;
    __shared__ __align__(16) float sA[NC];
    for (int i = threadIdx.x; i < NC; i += 256) sA[i] = A0[b * NC + i];
    __syncthreads();
    float acc = 0.f;
#pragma unroll 8
    for (int d = 0; d < NC; d++)
        acc += sA[d] * __ldg(M + (size_t)d * NC + c);
    out[b * NC + c] = acc;
}

// approx scores from fp16 Xhi
__global__ void __launch_bounds__(256)
dot_approx(const __half* __restrict__ Xhi)
{
    int b = blockIdx.y;
    __shared__ __align__(16) float su[NC];
    for (int i = threadIdx.x; i < NC; i += 256) su[i] = g_u[b * NC + i];
    __syncthreads();
    int warp = threadIdx.x >> 5, lane = threadIdx.x & 31;
    int l = blockIdx.x * 8 + warp;
    const float4* xr = (const float4*)(Xhi + ((size_t)b * NL + l) * NC);
    float acc = 0.f;
#pragma unroll 4
    for (int i = lane; i < NC / 8; i += 32) {
        float4 h8 = __ldg(&xr[i]);
        const __half2* hp = (const __half2*)&h8;
        const float4* u0 = (const float4*)&su[i * 8];
        float4 ua = u0[0], ub = u0[1];
        float2 p0 = __half22float2(hp[0]);
        float2 p1 = __half22float2(hp[1]);
        float2 p2 = __half22float2(hp[2]);
        float2 p3 = __half22float2(hp[3]);
        acc += p0.x * ua.x + p0.y * ua.y + p1.x * ua.z + p1.y * ua.w;
        acc += p2.x * ub.x + p2.y * ub.y + p3.x * ub.z + p3.y * ub.w;
    }
#pragma unroll
    for (int o = 16; o; o >>= 1) acc += __shfl_xor_sync(0xffffffffu, acc, o);
    if (lane == 0) g_s[b * NL + l] = acc;
}

// ---------------------------------------------------------------------------
// fused selection: top-24 approx -> exact fp32 rescue -> ordered top-20 ->
// gather+split selected rows. one 768-thread block per batch.
// NOTE: su declared FIRST and 16B-aligned (float4 casts below).
// ---------------------------------------------------------------------------
__global__ void __launch_bounds__(768)
select_kernel(const float* __restrict__ X0)
{
    __shared__ __align__(16) float su[NC];
    __shared__ __align__(16) float vals[NL];
    __shared__ float lmax[256];
    __shared__ int   lidx[256];
    __shared__ float wmax[8];
    __shared__ int   widx[8];
    __shared__ int   sowner;
    __shared__ int   scand[NCAND];
    __shared__ float sval[NCAND];
    __shared__ int   sidx[NCAND];
    __shared__ int   stop[KSEL];
    int b = blockIdx.x;
    int tid = threadIdx.x;
    int warp = tid >> 5, lane = tid & 31;

    for (int i = tid; i < NC; i += 768) su[i] = g_u[b * NC + i];
    for (int i = tid; i < NL; i += 768) vals[i] = g_s[b * NL + i];
    __syncthreads();

    // ---- phase 1: approx top-24 (threads 0..255 active) ----
    if (tid < 256) {
        float m = -FLT_MAX; int mi = 0x7fffffff;
#pragma unroll
        for (int r = 0; r < 8; r++) {
            int i = tid + r * 256;
            argmax2(m, mi, vals[i], i);
        }
        lmax[tid] = m; lidx[tid] = mi;
    }
    __syncthreads();
    for (int it = 0; it < NCAND; it++) {
        if (tid < 256) {
            float v = lmax[tid]; int i = lidx[tid];
#pragma unroll
            for (int o = 16; o; o >>= 1)
                argmax2(v, i, __shfl_xor_sync(0xffffffffu, v, o),
                              __shfl_xor_sync(0xffffffffu, i, o));
            if (lane == 0) { wmax[warp] = v; widx[warp] = i; }
        }
        __syncthreads();
        if (tid == 0) {
            float bv = wmax[0]; int bi = widx[0];
#pragma unroll
            for (int w = 1; w < 8; w++) argmax2(bv, bi, wmax[w], widx[w]);
            scand[it] = bi;
            vals[bi] = -FLT_MAX;
            sowner = bi & 255;
        }
        __syncthreads();
        if (tid == sowner) {
            float m = -FLT_MAX; int mi = 0x7fffffff;
#pragma unroll
            for (int r = 0; r < 8; r++) {
                int i2 = tid + r * 256;
                argmax2(m, mi, vals[i2], i2);
            }
            lmax[tid] = m; lidx[tid] = mi;
        }
        __syncthreads();
    }

    // ---- phase 2: exact fp32 dots of the 24 candidates (24 warps) ----
    if (warp < NCAND) {
        int l = scand[warp];
        const float4* xr = (const float4*)(X0 + ((size_t)b * NL + l) * NC);
        const float4* ur = (const float4*)su;
        float acc = 0.f;
#pragma unroll 4
        for (int i = lane; i < NC / 4; i += 32) {
            float4 x = __ldg(&xr[i]);
            float4 u = ur[i];
            acc += x.x * u.x + x.y * u.y + x.z * u.z + x.w * u.w;
        }
#pragma unroll
        for (int o = 16; o; o >>= 1) acc += __shfl_xor_sync(0xffffffffu, acc, o);
        if (lane == 0) { sval[warp] = acc; sidx[warp] = l; }
    }
    __syncthreads();
    if (warp == 0) {
        float v = (lane < NCAND) ? sval[lane] : -FLT_MAX;
        int i = (lane < NCAND) ? sidx[lane] : 0x7fffffff;
        for (int it = 0; it < KSEL; it++) {
            float bv = v; int bi = i;
#pragma unroll
            for (int o = 16; o; o >>= 1)
                argmax2(bv, bi, __shfl_xor_sync(0xffffffffu, bv, o),
                                __shfl_xor_sync(0xffffffffu, bi, o));
            if (i == bi && v == bv) v = -FLT_MAX;
            if (lane == 0) stop[it] = bi;
        }
    }
    __syncthreads();

    // ---- phase 3: gather + hi/lo split of the 20 selected rows ----
    for (int idx = tid; idx < KSEL * 256; idx += 768) {
        int r = idx >> 8, t = idx & 255;
        int l = stop[r];
        size_t dst = ((size_t)(b * KSEL + r)) * NC + t * 4;
        float4 v = *(const float4*)(X0 + ((size_t)b * NL + l) * NC + t * 4);
        __half h0 = __float2half_rn(v.x), h1 = __float2half_rn(v.y);
        __half h2 = __float2half_rn(v.z), h3 = __float2half_rn(v.w);
        __half2* hp = (__half2*)(g_xghi + dst);
        hp[0] = __halves2half2(h0, h1);
        hp[1] = __halves2half2(h2, h3);
        __half2* lp = (__half2*)(g_xglo + dst);
        lp[0] = __floats2half2_rn(v.x - __half2float(h0), v.y - __half2float(h1));
        lp[1] = __floats2half2_rn(v.z - __half2float(h2), v.w - __half2float(h3));
    }
}

// ---------------------------------------------------------------------------
// fp16x3 GEMM for selected rows: M-tile 64, N-tile 128, 8 warps 32x32.
// grid (8 ntiles, 10 mtiles) = 80 CTAs. 3-stage cp.async + ldmatrix.
// ---------------------------------------------------------------------------
#define ST3_BYTES 12288

template <int SPLIT>
__global__ void __launch_bounds__(256, 1)
gemm_x3(const __half* __restrict__ Ahi, const __half* __restrict__ Alo,
        const __half* __restrict__ Bhi, const __half* __restrict__ Blo,
        const float* __restrict__ bias, float* __restrict__ outf,
        __half* __restrict__ ohi, __half* __restrict__ olo)
{
    __shared__ char smem[3 * ST3_BYTES];
    const int tid = threadIdx.x;
    const int ntile = blockIdx.x, mtile = blockIdx.y;
    const int wid = tid >> 5, lane = tid & 31;
    const int wm = wid >> 2, wn = wid & 3;
    const int gr = lane >> 2, q = lane & 3;
    const uint32_t sbase = smem_u32(smem);

    const int arow = (tid & 127) >> 1, aseg = tid & 1;
    const int brow = tid >> 1, bseg = tid & 1;
    const size_t gA = (size_t)(mtile * 64 + arow) * NC + aseg * 8;
    const size_t gB = (size_t)(ntile * 128 + brow) * NC + bseg * 8;
    const uint32_t dstoA = arow * 32 + ((aseg * 16) ^ (((arow >> 2) & 1) * 16));
    const uint32_t dstoB = brow * 32 + ((bseg * 16) ^ (((brow >> 2) & 1) * 16));
    const bool doA = tid < 128;

    float acc[2][4][4];
#pragma unroll
    for (int i = 0; i < 2; i++)
#pragma unroll
        for (int j = 0; j < 4; j++)
#pragma unroll
            for (int r = 0; r < 4; r++) acc[i][j][r] = 0.f;

    const int arl = (lane & 7) + ((lane >> 3) & 1) * 8;
    const int ac = lane >> 4;
    uint32_t aoffs[2];
#pragma unroll
    for (int mt = 0; mt < 2; mt++) {
        int r = wm * 32 + mt * 16 + arl;
        aoffs[mt] = r * 32 + ((ac * 16) ^ (((r >> 2) & 1) * 16));
    }
    uint32_t boffs[2];
#pragma unroll
    for (int p = 0; p < 2; p++) {
        int g = lane >> 3;
        int n = wn * 32 + p * 16 + (g >> 1) * 8 + (lane & 7);
        int c = g & 1;
        boffs[p] = n * 32 + ((c * 16) ^ (((n >> 2) & 1) * 16));
    }

    auto issue = [&](int s, int k0) {
        uint32_t base = sbase + s * ST3_BYTES;
        if (doA) {
            CP_ASYNC16(base + dstoA,         Ahi + gA + k0);
            CP_ASYNC16(base + 2048u + dstoA, Alo + gA + k0);
        }
        CP_ASYNC16(base + 4096u + dstoB, Bhi + gB + k0);
        CP_ASYNC16(base + 8192u + dstoB, Blo + gB + k0);
    };

    issue(0, 0);  CP_COMMIT();
    issue(1, 16); CP_COMMIT();

    for (int ks = 0; ks < 64; ks++) {
        CP_WAIT1();
        __syncthreads();
        int s = ks % 3;
        if (ks < 62) issue((ks + 2) % 3, (ks + 2) * 16);
        CP_COMMIT();

        const uint32_t st = sbase + s * ST3_BYTES;
        uint32_t bh[8], bl[8];
        LDSM4(bh[0], bh[1], bh[2], bh[3], st + 4096u + boffs[0]);
        LDSM4(bh[4], bh[5], bh[6], bh[7], st + 4096u + boffs[1]);
        LDSM4(bl[0], bl[1], bl[2], bl[3], st + 8192u + boffs[0]);
        LDSM4(bl[4], bl[5], bl[6], bl[7], st + 8192u + boffs[1]);
#pragma unroll
        for (int mt = 0; mt < 2; mt++) {
            uint32_t H0, H1, H2, H3, L0, L1, L2, L3;
            LDSM4(H0, H1, H2, H3, st + aoffs[mt]);
#pragma unroll
            for (int nt = 0; nt < 4; nt++)
                MMA16816(acc[mt][nt], H0, H1, H2, H3, bh[nt * 2], bh[nt * 2 + 1]);
#pragma unroll
            for (int nt = 0; nt < 4; nt++)
                MMA16816(acc[mt][nt], H0, H1, H2, H3, bl[nt * 2], bl[nt * 2 + 1]);
            LDSM4(L0, L1, L2, L3, st + 2048u + aoffs[mt]);
#pragma unroll
            for (int nt = 0; nt < 4; nt++)
                MMA16816(acc[mt][nt], L0, L1, L2, L3, bh[nt * 2], bh[nt * 2 + 1]);
        }
    }

#pragma unroll
    for (int mt = 0; mt < 2; mt++)
#pragma unroll
        for (int nt = 0; nt < 4; nt++)
#pragma unroll
            for (int r = 0; r < 4; r++) {
                int m = mtile * 64 + wm * 32 + mt * 16 + gr + 8 * (r >> 1);
                int n = ntile * 128 + wn * 32 + nt * 8 + q * 2 + (r & 1);
                float v = acc[mt][nt][r] + __ldg(bias + n);
                if (SPLIT) {
                    __half h = __float2half_rn(v);
                    ohi[(size_t)m * NC + n] = h;
                    olo[(size_t)m * NC + n] =
                        __float2half_rn(v - __half2float(h));
                } else {
                    outf[(size_t)m * NC + n] = v;
                }
            }
}

// ---------------------------------------------------------------------------
static void* symp(const void* symbol)
{
    void* p = nullptr;
    cudaGetSymbolAddress(&p, symbol);
    return p;
}

extern "C" void kernel_launch(void* const* d_in, const int* in_sizes, int n_in,
                              void* d_out, int out_size)
{
    const float* x0  = (const float*)d_in[0];
    const float* W   = (const float*)d_in[1];
    const float* b   = (const float*)d_in[2];
    const float* W1  = (const float*)d_in[3];
    const float* b1  = (const float*)d_in[4];
    const float* Wm  = (const float*)d_in[5];
    const float* bm  = (const float*)d_in[6];
    const float* Wa  = (const float*)d_in[7];
    const float* ba  = (const float*)d_in[8];
    const float* g1w = (const float*)d_in[9];
    const float* g1b = (const float*)d_in[10];
    const float* g2w = (const float*)d_in[11];
    const float* g2b = (const float*)d_in[12];
    float* out = (float*)d_out;

    __half* p_Xhi  = (__half*)symp(g_Xhi);
    __half* p_Whi  = (__half*)symp(g_Whi);
    __half* p_Wlo  = (__half*)symp(g_Wlo);
    __half* p_W1hi = (__half*)symp(g_W1hi);
    __half* p_W1lo = (__half*)symp(g_W1lo);
    __half* p_xghi = (__half*)symp(g_xghi);
    __half* p_xglo = (__half*)symp(g_xglo);
    __half* p_yhi  = (__half*)symp(g_yhi);
    __half* p_ylo  = (__half*)symp(g_ylo);
    float* p_colmean = (float*)symp(g_colmean);
    float* p_xmean = (float*)symp(g_xmean);
    float* p_xA    = (float*)symp(g_xA);
    float* p_tM    = (float*)symp(g_tM);
    float* p_tA    = (float*)symp(g_tA);
    float* p_v     = (float*)symp(g_v);
    float* p_u     = (float*)symp(g_u);

    // 0) splits + one-shot colmean reduce
    split_colsum<<<NB * 128, 256>>>(x0, p_Xhi);
    dim3 gws((NC * NC / 4) / 256, 2);
    wsplit2<<<gws, 256>>>(W, W1);
    colmean_reduce<<<(NB * NC) / 256, 256>>>();

    // 1) approx GEMM1 + fused candidate-reduce/exact-max (top-2)
    dim3 g1(8, 512);
    gemm1_mma<<<g1, 256>>>(p_Xhi, p_Whi);
    dim3 gex(NC / 8, NB);
    exact_max<<<gex, 256>>>(x0, W, b);

    // 2) mean path + pooled branches
    dim3 gst(NC / 8, NB);
    small_gemm_T<<<gst, 256>>>(p_colmean, W, b, p_xmean);
    dim3 gst2(NC / 8, NB, 2);
    small_gemm_T2<<<gst2, 256>>>(p_xmean, Wm, bm, p_tM, p_xA, Wa, ba, p_tA);

    // 3) v = W1^T(gn1+gn2) with inline GroupNorm; u = W^T v
    dim3 gsn(NC / 256, NB);
    gemmN_gn<<<gsn, 256>>>(g1w, g1b, g2w, g2b, W1, p_v);
    small_gemm_N<<<gsn, 256>>>(p_v, W, p_u);

    // 4) approx scores, fused top-24/rescue/gather, fp16x3 recompute
    dim3 gdot(NL / 8, NB);
    dot_approx<<<gdot, 256>>>(p_Xhi);
    select_kernel<<<NB, 768>>>(x0);
    dim3 gg2(8, (NB * KSEL) / 64);
    gemm_x3<1><<<gg2, 256>>>(p_xghi, p_xglo, p_Whi, p_Wlo, b,
                             nullptr, p_yhi, p_ylo);
    gemm_x3<0><<<gg2, 256>>>(p_yhi, p_ylo, p_W1hi, p_W1lo, b1,
                             out, nullptr, nullptr);
}